// round 9
// baseline (speedup 1.0000x reference)
#include <cuda_runtime.h>
#include <cstdint>

#define NB   64      // B
#define NP   2048    // P
#define NL   512     // L
#define NDM  512     // D_MODEL
#define NH   8       // heads
#define NDK  64
#define SPLIT 2
#define ROWS_PER_BLK (NP/SPLIT)    // 1024
#define TILE 32
#define NTILES (ROWS_PER_BLK/TILE) // 32

#define NEG_INF (__int_as_float(0xff800000))

// ------------------------- scratch (static device memory) -------------------------
__device__ float g_ug[NB*NH*NL];         // (u * lnkv_g) per (b,h,l)
__device__ float g_ugs[NB*NH];           // sum_l ug
__device__ float g_ub[NB*NH];            // sum_l u * lnkv_b
__device__ float g_scores[NB*NH*NP];     // raw scores
__device__ float g_pm[NB*SPLIT*NH];      // partial max
__device__ float g_pz[NB*SPLIT*NH];      // partial Z
__device__ float g_pt[NB*SPLIT*NH];      // partial T
__device__ float g_pa[NB*SPLIT*NH*NL];   // partial A (2 MB)
__device__ float g_res[NB*NDM];          // residual = x_trafic @ res_W + res_b

// ------------------------- helpers -------------------------
__device__ __forceinline__ uint32_t s2u(const void* p) {
    return (uint32_t)__cvta_generic_to_shared(p);
}
__device__ __forceinline__ void cp_async16(uint32_t s, const void* g) {
    asm volatile("cp.async.cg.shared.global [%0], [%1], 16;\n" :: "r"(s), "l"(g));
}
#define CP_COMMIT() asm volatile("cp.async.commit_group;\n")
#define CP_WAIT1()  asm volatile("cp.async.wait_group 1;\n")
#define CP_WAIT0()  asm volatile("cp.async.wait_group 0;\n")

// packed fp32x2 math (Blackwell; ptxas never emits these from C++)
__device__ __forceinline__ unsigned long long fma2(unsigned long long a,
                                                   unsigned long long b,
                                                   unsigned long long c) {
    unsigned long long d;
    asm("fma.rn.f32x2 %0, %1, %2, %3;" : "=l"(d) : "l"(a), "l"(b), "l"(c));
    return d;
}
__device__ __forceinline__ unsigned long long add2(unsigned long long a,
                                                   unsigned long long b) {
    unsigned long long d;
    asm("add.rn.f32x2 %0, %1, %2;" : "=l"(d) : "l"(a), "l"(b));
    return d;
}
__device__ __forceinline__ unsigned long long mul2(unsigned long long a,
                                                   unsigned long long b) {
    unsigned long long d;
    asm("mul.rn.f32x2 %0, %1, %2;" : "=l"(d) : "l"(a), "l"(b));
    return d;
}
__device__ __forceinline__ unsigned long long pack2(float lo, float hi) {
    unsigned long long d;
    asm("mov.b64 %0, {%1, %2};" : "=l"(d) : "f"(lo), "f"(hi));
    return d;
}
__device__ __forceinline__ float fold2(unsigned long long a) {
    float lo, hi;
    asm("mov.b64 {%0, %1}, %2;" : "=f"(lo), "=f"(hi) : "l"(a));
    return lo + hi;
}

// =========================================================================
// Kernel 1: blocks 0..63   : per batch b: Q/u prep -> g_ug, g_ugs, g_ub
//           blocks 64..127 : residual GEMV -> g_res
// =========================================================================
__global__ void __launch_bounds__(512) k1_prep(
    const float* __restrict__ x_trafic,
    const float* __restrict__ W_q, const float* __restrict__ W_k,
    const float* __restrict__ lnq_g, const float* __restrict__ lnq_b,
    const float* __restrict__ lnkv_g, const float* __restrict__ lnkv_b,
    const float* __restrict__ res_W, const float* __restrict__ res_b)
{
    __shared__ float  lnq_s[NL];
    __shared__ float4 Q_s4[NL/4];
    __shared__ float4 part4[4*128];
    __shared__ float  red1[16], red2[16];
    __shared__ float  sc_mean, sc_r;
    __shared__ float  ugs_sm[NH], ub_sm[NH];

    const int t = threadIdx.x;
    const int lane = t & 31, wid = t >> 5;

    if (blockIdx.x >= NB) {
        // ---------------- residual GEMV: g_res[b] = x_t[b] @ res_W + res_b -------
        const int b = blockIdx.x - NB;
        lnq_s[t] = x_trafic[b*NL + t];
        __syncthreads();
        const int og = t & 127, lg = t >> 7;
        const float4* W4 = (const float4*)res_W;
        float4 acc = {0,0,0,0};
        const int l0 = lg * 128;
        #pragma unroll 4
        for (int l = l0; l < l0 + 128; l++) {
            float s = lnq_s[l];
            float4 w = W4[l*128 + og];
            acc.x += s*w.x; acc.y += s*w.y; acc.z += s*w.z; acc.w += s*w.w;
        }
        part4[lg*128 + og] = acc;
        __syncthreads();
        if (t < 128) {
            float4 a = part4[t], b2 = part4[128+t], c = part4[256+t], d = part4[384+t];
            float4 rb = ((const float4*)res_b)[t];
            float4 o;
            o.x = a.x + b2.x + c.x + d.x + rb.x;
            o.y = a.y + b2.y + c.y + d.y + rb.y;
            o.z = a.z + b2.z + c.z + d.z + rb.z;
            o.w = a.w + b2.w + c.w + d.w + rb.w;
            ((float4*)g_res)[b*128 + t] = o;
        }
        return;
    }

    const int b = blockIdx.x;
    if (t < NH) { ugs_sm[t] = 0.f; ub_sm[t] = 0.f; }

    // LN stats of x_trafic row
    float v = x_trafic[b*NL + t];
    float s1 = v, s2v = v*v;
    #pragma unroll
    for (int o = 16; o > 0; o >>= 1) {
        s1  += __shfl_xor_sync(~0u, s1, o);
        s2v += __shfl_xor_sync(~0u, s2v, o);
    }
    if (lane == 0) { red1[wid] = s1; red2[wid] = s2v; }
    __syncthreads();
    if (t == 0) {
        float a = 0.f, c = 0.f;
        #pragma unroll
        for (int i = 0; i < 16; i++) { a += red1[i]; c += red2[i]; }
        float mean = a * (1.f/NL);
        float var  = c * (1.f/NL) - mean*mean;
        sc_mean = mean;
        sc_r = rsqrtf(var + 1e-5f);
    }
    __syncthreads();
    lnq_s[t] = (v - sc_mean) * sc_r * lnq_g[t] + lnq_b[t];
    __syncthreads();

    // Q = lnq @ W_q
    {
        const int og = t & 127, lg = t >> 7;
        const float4* Wq4 = (const float4*)W_q;
        float4 acc = {0,0,0,0};
        const int l0 = lg * 128;
        #pragma unroll 4
        for (int l = l0; l < l0 + 128; l++) {
            float s = lnq_s[l];
            float4 w = Wq4[l*128 + og];
            acc.x += s*w.x; acc.y += s*w.y; acc.z += s*w.z; acc.w += s*w.w;
        }
        part4[lg*128 + og] = acc;
    }
    __syncthreads();
    if (t < 128) {
        float4 a = part4[t], b2 = part4[128+t], c = part4[256+t], d = part4[384+t];
        a.x += b2.x + c.x + d.x;
        a.y += b2.y + c.y + d.y;
        a.z += b2.z + c.z + d.z;
        a.w += b2.w + c.w + d.w;
        Q_s4[t] = a;
    }
    __syncthreads();

    // u[h,l]
    const float4* Wk4 = (const float4*)W_k;
    const int h = lane >> 2;
    float ugs_p = 0.f, ub_p = 0.f;
    for (int it = 0; it < 32; it++) {
        int l = wid + 16*it;
        float acc = 0.f;
        #pragma unroll
        for (int j = 0; j < 4; j++) {
            float4 w = Wk4[l*128 + lane*4 + j];
            float4 q = Q_s4[lane*4 + j];
            acc += w.x*q.x + w.y*q.y + w.z*q.z + w.w*q.w;
        }
        acc += __shfl_xor_sync(~0u, acc, 1);
        acc += __shfl_xor_sync(~0u, acc, 2);
        if ((lane & 3) == 0) {
            float ug = acc * lnkv_g[l];
            g_ug[(b*NH + h)*NL + l] = ug;
            ugs_p += ug;
            ub_p  += acc * lnkv_b[l];
        }
    }
    if ((lane & 3) == 0) {
        atomicAdd(&ugs_sm[h], ugs_p);
        atomicAdd(&ub_sm[h], ub_p);
    }
    __syncthreads();
    if (t < NH) {
        g_ugs[b*NH + t] = ugs_sm[t];
        g_ub [b*NH + t] = ub_sm[t];
    }
}

// =========================================================================
// Kernel 2: main fused pass over x_dynamic, f32x2 packed math.
//  phase3: 8 warps x 4 rows, single pass over all 8 heads, f32x2 FMA
//  phase4: 1 warp per head
//  phase5: f32x2 FMA, ea fetched as broadcast float4
// =========================================================================
__global__ void __launch_bounds__(512, 1) k2_main(const float* __restrict__ x_dyn)
{
    extern __shared__ float sm[];
    float* buf     = sm;                     // 2*32*512 = 32768
    float* ug_s    = sm + 2*TILE*NL;         // 4096
    float* sc_s    = ug_s + NH*NL;           // 256 [h][p]
    float* ea_s    = sc_s + NH*TILE;         // 256 [h][p]
    float* scale_s = ea_s + NH*TILE;         // 8
    float* mrow_s  = scale_s + NH;           // 32
    float* rrow_s  = mrow_s + TILE;          // 32
    float* mrun_s  = rrow_s + TILE;          // 8
    float* zrun_s  = mrun_s + NH;            // 8
    float* trun_s  = zrun_s + NH;            // 8
    float* ugs_s   = trun_s + NH;            // 8
    float* ub_s    = ugs_s + NH;             // 8

    const int t = threadIdx.x;
    const int split = blockIdx.x, b = blockIdx.y;
    const int lane = t & 31, wid = t >> 5;

    // load ug for this b (4096 floats)
    {
        const float4* gug4 = (const float4*)(g_ug + (size_t)b*NH*NL);
        float4* ug4 = (float4*)ug_s;
        ug4[t]       = gug4[t];
        ug4[t + 512] = gug4[t + 512];
    }
    if (t < NH) {
        ugs_s[t] = g_ugs[b*NH + t];
        ub_s [t] = g_ub [b*NH + t];
        mrun_s[t] = NEG_INF; zrun_s[t] = 0.f; trun_s[t] = 0.f;
    }

    const float* xbase = x_dyn + ((size_t)b*NP + (size_t)split*ROWS_PER_BLK)*NL;

    // prefetch tile 0 (32*512 floats = 4096 float4; 8 per thread)
    {
        uint32_t dst = s2u(buf);
        const float4* src = (const float4*)xbase;
        #pragma unroll
        for (int j = 0; j < 8; j++)
            cp_async16(dst + (uint32_t)(t + 512*j)*16u, src + t + 512*j);
        CP_COMMIT();
    }

    // phase5 thread mapping
    const int cg = t & 127;           // 16B column group
    const int hg = (t >> 7) & 1;      // head group: heads hg*4..hg*4+3
    const int pg = t >> 8;            // p half: [pg*16, pg*16+16)
    ulonglong2 A2[4];
    #pragma unroll
    for (int j = 0; j < 4; j++) { A2[j].x = 0ull; A2[j].y = 0ull; }

    #pragma unroll 1
    for (int tile = 0; tile < NTILES; tile++) {
        float* xb = buf + (tile & 1)*TILE*NL;

        __syncthreads();   // prev phase5 done: safe to refill other buffer / rewrite ea_s

        if (tile + 1 < NTILES) {
            float* nb = buf + ((tile+1) & 1)*TILE*NL;
            uint32_t dst = s2u(nb);
            const float4* src = (const float4*)(xbase + (size_t)(tile+1)*TILE*NL);
            #pragma unroll
            for (int j = 0; j < 8; j++)
                cp_async16(dst + (uint32_t)(t + 512*j)*16u, src + t + 512*j);
            CP_COMMIT();
            CP_WAIT1();
        } else {
            CP_WAIT0();
        }
        __syncthreads();   // tile data visible

        // ---- phase 3: warps 0..7, warp w handles rows w*4..w*4+3, f32x2 ----
        if (wid < 8) {
            const ulonglong2* xw2 = (const ulonglong2*)xb + (wid*4)*128;
            const ulonglong2* ug2 = (const ulonglong2*)ug_s;
            unsigned long long d2[4][8];
            unsigned long long s2[4], q2[4];
            #pragma unroll
            for (int r = 0; r < 4; r++) {
                s2[r] = 0ull; q2[r] = 0ull;
                #pragma unroll
                for (int h = 0; h < 8; h++) d2[r][h] = 0ull;
            }
            #pragma unroll
            for (int i = 0; i < 4; i++) {
                const int idx = lane + 32*i;
                ulonglong2 u[8];
                #pragma unroll
                for (int h = 0; h < 8; h++) u[h] = ug2[h*128 + idx];
                #pragma unroll
                for (int r = 0; r < 4; r++) {
                    ulonglong2 v = xw2[r*128 + idx];
                    s2[r] = add2(s2[r], v.x);
                    s2[r] = add2(s2[r], v.y);
                    q2[r] = fma2(v.x, v.x, q2[r]);
                    q2[r] = fma2(v.y, v.y, q2[r]);
                    #pragma unroll
                    for (int h = 0; h < 8; h++) {
                        d2[r][h] = fma2(v.x, u[h].x, d2[r][h]);
                        d2[r][h] = fma2(v.y, u[h].y, d2[r][h]);
                    }
                }
            }
            float dd[32], st[8];
            #pragma unroll
            for (int r = 0; r < 4; r++) {
                st[r]   = fold2(s2[r]);
                st[4+r] = fold2(q2[r]);
                #pragma unroll
                for (int h = 0; h < 8; h++) dd[r*8+h] = fold2(d2[r][h]);
            }

            // butterfly multi-value reduce: lane k ends with sum of dd[k]
            #pragma unroll
            for (int o = 16; o >= 1; o >>= 1) {
                #pragma unroll
                for (int i = 0; i < o; i++) {
                    bool hi = (lane & o) != 0;
                    float mine   = hi ? dd[i+o] : dd[i];
                    float theirs = hi ? dd[i]   : dd[i+o];
                    dd[i] = mine + __shfl_xor_sync(0xffffffffu, theirs, o);
                }
            }
            // stats: lane k ends with st[k&7]
            #pragma unroll
            for (int o = 16; o >= 8; o >>= 1) {
                #pragma unroll
                for (int i = 0; i < 8; i++)
                    st[i] += __shfl_xor_sync(0xffffffffu, st[i], o);
            }
            #pragma unroll
            for (int o = 4; o >= 1; o >>= 1) {
                #pragma unroll
                for (int i = 0; i < o; i++) {
                    bool hi = (lane & o) != 0;
                    float mine   = hi ? st[i+o] : st[i];
                    float theirs = hi ? st[i]   : st[i+o];
                    st[i] = mine + __shfl_xor_sync(0xffffffffu, theirs, o);
                }
            }

            const int r = lane >> 3, h = lane & 7;
            float sfin = st[0];
            float mean = __shfl_sync(0xffffffffu, sfin, r) * (1.f/NL);
            float sqv  = __shfl_sync(0xffffffffu, sfin, r + 4) * (1.f/NL);
            float var  = sqv - mean*mean;
            float rs   = rsqrtf(var + 1e-5f);
            float s = (rs * (dd[0] - mean * ugs_s[h]) + ub_s[h]) * 0.125f;
            const int prow = wid*4 + r;
            sc_s[h*TILE + prow] = s;
            if (h == 0) { mrow_s[prow] = mean; rrow_s[prow] = rs; }
        }
        __syncthreads();

        // ---- phase 4: warp w = head w, lanes over p ----
        if (wid < 8) {
            const int h = wid, p = lane;
            float s = sc_s[h*TILE + p];
            float mr = mrun_s[h];
            float tmax = s;
            #pragma unroll
            for (int o = 16; o > 0; o >>= 1)
                tmax = fmaxf(tmax, __shfl_xor_sync(~0u, tmax, o));
            float mn = fmaxf(mr, tmax);
            float e  = __expf(s - mn);
            float ea = e * rrow_s[p];
            float z = e, tt = ea * mrow_s[p];
            #pragma unroll
            for (int o = 16; o > 0; o >>= 1) {
                z  += __shfl_xor_sync(~0u, z,  o);
                tt += __shfl_xor_sync(~0u, tt, o);
            }
            ea_s[h*TILE + p] = ea;
            g_scores[((size_t)(b*NH + h))*NP + split*ROWS_PER_BLK + tile*TILE + p] = s;
            if (lane == 0) {
                float scale = __expf(mr - mn);
                zrun_s[h] = zrun_s[h]*scale + z;
                trun_s[h] = trun_s[h]*scale + tt;
                mrun_s[h] = mn;
                scale_s[h] = scale;
            }
        }
        __syncthreads();

        // ---- phase 5: accumulate A, f32x2 ----
        {
            #pragma unroll
            for (int j = 0; j < 4; j++) {
                float sj = scale_s[hg*4 + j];
                unsigned long long sj2 = pack2(sj, sj);
                A2[j].x = mul2(A2[j].x, sj2);
                A2[j].y = mul2(A2[j].y, sj2);
            }
            const ulonglong2* xc2 = (const ulonglong2*)xb;
            #pragma unroll
            for (int pq = 0; pq < 4; pq++) {
                const int p0 = pg*16 + pq*4;
                float4 e0 = *(const float4*)&ea_s[(hg*4+0)*TILE + p0];
                float4 e1 = *(const float4*)&ea_s[(hg*4+1)*TILE + p0];
                float4 e2 = *(const float4*)&ea_s[(hg*4+2)*TILE + p0];
                float4 e3 = *(const float4*)&ea_s[(hg*4+3)*TILE + p0];
                float ev0[4] = {e0.x, e0.y, e0.z, e0.w};
                float ev1[4] = {e1.x, e1.y, e1.z, e1.w};
                float ev2[4] = {e2.x, e2.y, e2.z, e2.w};
                float ev3[4] = {e3.x, e3.y, e3.z, e3.w};
                #pragma unroll
                for (int pp = 0; pp < 4; pp++) {
                    ulonglong2 v = xc2[(p0+pp)*128 + cg];
                    unsigned long long q0 = pack2(ev0[pp], ev0[pp]);
                    unsigned long long q1 = pack2(ev1[pp], ev1[pp]);
                    unsigned long long q2_ = pack2(ev2[pp], ev2[pp]);
                    unsigned long long q3 = pack2(ev3[pp], ev3[pp]);
                    A2[0].x = fma2(q0, v.x, A2[0].x);  A2[0].y = fma2(q0, v.y, A2[0].y);
                    A2[1].x = fma2(q1, v.x, A2[1].x);  A2[1].y = fma2(q1, v.y, A2[1].y);
                    A2[2].x = fma2(q2_, v.x, A2[2].x); A2[2].y = fma2(q2_, v.y, A2[2].y);
                    A2[3].x = fma2(q3, v.x, A2[3].x);  A2[3].y = fma2(q3, v.y, A2[3].y);
                }
            }
        }
    }

    // epilogue: combine the two p-halves via smem (ug_s no longer needed)
    __syncthreads();
    if (pg == 1) {
        float4* tmp = (float4*)ug_s;
        #pragma unroll
        for (int j = 0; j < 4; j++) tmp[(hg*4+j)*128 + cg] = *(float4*)&A2[j];
    }
    __syncthreads();
    if (pg == 0) {
        const float4* tmp = (const float4*)ug_s;
        float4* pa = (float4*)(g_pa + (size_t)(b*SPLIT + split)*NH*NL);
        #pragma unroll
        for (int j = 0; j < 4; j++) {
            float4 o = tmp[(hg*4+j)*128 + cg];
            float4 a = *(float4*)&A2[j];
            o.x += a.x; o.y += a.y; o.z += a.z; o.w += a.w;
            pa[(hg*4+j)*128 + cg] = o;
        }
    }
    if (t < NH) {
        int idx = (b*SPLIT + split)*NH + t;
        g_pm[idx] = mrun_s[t];
        g_pz[idx] = zrun_s[t];
        g_pt[idx] = trun_s[t];
    }
}

// =========================================================================
// Kernel 3: combine split partials per (b,h); project through W_v;
//           write out = residual + ctx; write normalized attn row
// =========================================================================
__global__ void __launch_bounds__(256) k3_combine(
    const float* __restrict__ W_v,
    const float* __restrict__ lnkv_g, const float* __restrict__ lnkv_b,
    float* __restrict__ out)
{
    __shared__ float es[SPLIT];
    __shared__ float sT, sInvZ, sM;
    __shared__ float cvec[NL];
    __shared__ float part[4*64];

    const int t = threadIdx.x;
    const int b = blockIdx.x >> 3, h = blockIdx.x & 7;

    if (t == 0) {
        float M = NEG_INF;
        #pragma unroll
        for (int i = 0; i < SPLIT; i++)
            M = fmaxf(M, g_pm[(b*SPLIT + i)*NH + h]);
        float Z = 0.f, T = 0.f;
        #pragma unroll
        for (int i = 0; i < SPLIT; i++) {
            int idx = (b*SPLIT + i)*NH + h;
            float e = __expf(g_pm[idx] - M);
            es[i] = e;
            Z += g_pz[idx] * e;
            T += g_pt[idx] * e;
        }
        float iz = 1.f / Z;
        sT = T; sInvZ = iz; sM = M;
    }
    __syncthreads();

    for (int l = t; l < NL; l += 256) {
        float A = 0.f;
        #pragma unroll
        for (int i = 0; i < SPLIT; i++)
            A += g_pa[((size_t)(b*SPLIT + i)*NH + h)*NL + l] * es[i];
        cvec[l] = lnkv_g[l] * (A - sT) * sInvZ + lnkv_b[l];
    }
    __syncthreads();

    {
        const int d = t & 63, lg = t >> 6;
        float acc = 0.f;
        const int l0 = lg * 128;
        #pragma unroll 4
        for (int l = l0; l < l0 + 128; l++)
            acc += cvec[l] * W_v[l*NDM + h*NDK + d];
        part[lg*64 + d] = acc;
    }
    __syncthreads();
    if (t < 64) {
        float c = part[t] + part[64+t] + part[128+t] + part[192+t];
        out[b*NDM + h*NDK + t] = c + g_res[b*NDM + h*NDK + t];
    }

    // attn output row for this (b,h): exp(score - M) * invZ
    {
        const float M = sM, iz = sInvZ;
        const float4* sc4 = (const float4*)(g_scores + ((size_t)(b*NH + h))*NP);
        float4* ao = (float4*)(out + NB*NDM + ((size_t)(b*NH + h))*NP);
        #pragma unroll
        for (int j = t; j < NP/4; j += 256) {
            float4 s = sc4[j];
            float4 o;
            o.x = __expf(s.x - M) * iz;
            o.y = __expf(s.y - M) * iz;
            o.z = __expf(s.z - M) * iz;
            o.w = __expf(s.w - M) * iz;
            ao[j] = o;
        }
    }
}

// =========================================================================
extern "C" void kernel_launch(void* const* d_in, const int* in_sizes, int n_in,
                              void* d_out, int out_size)
{
    const float* x_trafic  = (const float*)d_in[0];
    const float* x_dynamic = (const float*)d_in[1];
    // d_in[2] x_known unused by the reference
    const float* W_q    = (const float*)d_in[3];
    const float* W_k    = (const float*)d_in[4];
    const float* W_v    = (const float*)d_in[5];
    const float* lnq_g  = (const float*)d_in[6];
    const float* lnq_b  = (const float*)d_in[7];
    const float* lnkv_g = (const float*)d_in[8];
    const float* lnkv_b = (const float*)d_in[9];
    const float* res_W  = (const float*)d_in[10];
    const float* res_b  = (const float*)d_in[11];
    float* out = (float*)d_out;

    const int smem2 = (2*TILE*NL + NH*NL + 2*NH*TILE + NH + 2*TILE + 5*NH) * (int)sizeof(float);
    cudaFuncSetAttribute(k2_main, cudaFuncAttributeMaxDynamicSharedMemorySize, smem2);

    k1_prep<<<2*NB, 512>>>(x_trafic, W_q, W_k, lnq_g, lnq_b, lnkv_g, lnkv_b, res_W, res_b);
    k2_main<<<dim3(SPLIT, NB), 512, smem2>>>(x_dynamic);
    k3_combine<<<NB*NH, 256>>>(W_v, lnkv_g, lnkv_b, out);
}

// round 10
// speedup vs baseline: 1.2189x; 1.2189x over previous
#include <cuda_runtime.h>
#include <cstdint>

#define NB   64      // B
#define NP   2048    // P
#define NL   512     // L
#define NDM  512     // D_MODEL
#define NH   8       // heads
#define NDK  64
#define SPLIT 2
#define ROWS_PER_BLK (NP/SPLIT)    // 1024
#define TILE 32
#define NTILES (ROWS_PER_BLK/TILE) // 32
#define SCP  36      // padded row stride for sc_s/ea_s (bank-conflict-free, 16B-aligned)

#define NEG_INF (__int_as_float(0xff800000))

// ------------------------- scratch (static device memory) -------------------------
__device__ float g_lnq[NB*NL];           // LN(x_trafic) * g + b
__device__ float g_Q[NB*NDM];            // Q = lnq @ W_q
__device__ float g_ug[NB*NH*NL];         // (u * lnkv_g) per (b,h,l)
__device__ float g_ugs[NB*NH];           // sum_l ug
__device__ float g_ub[NB*NH];            // sum_l u * lnkv_b
__device__ float g_scores[NB*NH*NP];     // raw scores
__device__ float g_pm[NB*SPLIT*NH];      // partial max
__device__ float g_pz[NB*SPLIT*NH];      // partial Z
__device__ float g_pt[NB*SPLIT*NH];      // partial T
__device__ float g_pa[NB*SPLIT*NH*NL];   // partial A (2 MB)
__device__ float g_res[NB*NDM];          // residual = x_trafic @ res_W + res_b

// ------------------------- helpers -------------------------
__device__ __forceinline__ uint32_t s2u(const void* p) {
    return (uint32_t)__cvta_generic_to_shared(p);
}
__device__ __forceinline__ void cp_async16(uint32_t s, const void* g) {
    asm volatile("cp.async.cg.shared.global [%0], [%1], 16;\n" :: "r"(s), "l"(g));
}
#define CP_COMMIT() asm volatile("cp.async.commit_group;\n")
#define CP_WAIT1()  asm volatile("cp.async.wait_group 1;\n")
#define CP_WAIT0()  asm volatile("cp.async.wait_group 0;\n")

// packed fp32x2 math (Blackwell; ptxas never emits these from C++)
__device__ __forceinline__ unsigned long long fma2(unsigned long long a,
                                                   unsigned long long b,
                                                   unsigned long long c) {
    unsigned long long d;
    asm("fma.rn.f32x2 %0, %1, %2, %3;" : "=l"(d) : "l"(a), "l"(b), "l"(c));
    return d;
}
__device__ __forceinline__ unsigned long long add2(unsigned long long a,
                                                   unsigned long long b) {
    unsigned long long d;
    asm("add.rn.f32x2 %0, %1, %2;" : "=l"(d) : "l"(a), "l"(b));
    return d;
}
__device__ __forceinline__ unsigned long long mul2(unsigned long long a,
                                                   unsigned long long b) {
    unsigned long long d;
    asm("mul.rn.f32x2 %0, %1, %2;" : "=l"(d) : "l"(a), "l"(b));
    return d;
}
__device__ __forceinline__ unsigned long long pack2(float lo, float hi) {
    unsigned long long d;
    asm("mov.b64 %0, {%1, %2};" : "=l"(d) : "f"(lo), "f"(hi));
    return d;
}
__device__ __forceinline__ float fold2(unsigned long long a) {
    float lo, hi;
    asm("mov.b64 {%0, %1}, %2;" : "=f"(lo), "=f"(hi) : "l"(a));
    return lo + hi;
}

// =========================================================================
// Kernel 1a: LN of x_trafic -> g_lnq; zero ugs/ub accumulators.
// =========================================================================
__global__ void __launch_bounds__(512) k1a_ln(
    const float* __restrict__ x_trafic,
    const float* __restrict__ lnq_g, const float* __restrict__ lnq_b)
{
    __shared__ float red1[16], red2[16];
    __shared__ float sc_mean, sc_r;
    const int t = threadIdx.x, b = blockIdx.x;
    const int lane = t & 31, wid = t >> 5;

    if (b == 0) { g_ugs[t] = 0.f; g_ub[t] = 0.f; }   // NB*NH == 512

    float v = x_trafic[b*NL + t];
    float s1 = v, s2v = v*v;
    #pragma unroll
    for (int o = 16; o > 0; o >>= 1) {
        s1  += __shfl_xor_sync(~0u, s1, o);
        s2v += __shfl_xor_sync(~0u, s2v, o);
    }
    if (lane == 0) { red1[wid] = s1; red2[wid] = s2v; }
    __syncthreads();
    if (t == 0) {
        float a = 0.f, c = 0.f;
        #pragma unroll
        for (int i = 0; i < 16; i++) { a += red1[i]; c += red2[i]; }
        float mean = a * (1.f/NL);
        float var  = c * (1.f/NL) - mean*mean;
        sc_mean = mean;
        sc_r = rsqrtf(var + 1e-5f);
    }
    __syncthreads();
    g_lnq[b*NL + t] = (v - sc_mean) * sc_r * lnq_g[t] + lnq_b[t];
}

// =========================================================================
// Kernel 1b: two GEMMs C[64x512] = A @ W, W-slice shared across all b.
//   type 0 (blocks 0..63):   Q   = g_lnq    @ W_q
//   type 1 (blocks 64..127): res = x_trafic @ res_W + res_b
// Block = 8 output cols x all 64 b. smem: A (padded, K-interleaved) + W^T tile.
// =========================================================================
__global__ void __launch_bounds__(512) k1b_gemm(
    const float* __restrict__ x_trafic,
    const float* __restrict__ W_q, const float* __restrict__ res_W,
    const float* __restrict__ res_b)
{
    extern __shared__ float4 sm4[];
    float4* A4 = sm4;                 // [j=128][b=64] stride 65 (padded)
    float4* W4 = sm4 + 128*65;        // [j=128][c=8]
    const int t = threadIdx.x;
    const int type = blockIdx.x >> 6, cg = blockIdx.x & 63;
    const int c0 = cg * 8;
    const float* A = type ? x_trafic : g_lnq;
    const float* W = type ? res_W : W_q;

    // load A: coalesced read, scatter to [j][b] with row stride 65
    {
        const float4* Asrc = (const float4*)A;
        #pragma unroll
        for (int k = 0; k < 16; k++) {
            int g = t + 512*k;                     // < 8192
            A4[(g & 127)*65 + (g >> 7)] = Asrc[g];
        }
    }
    // load W slice [512 l][8 c], transpose to W4[j][c] (element = l&3)
    {
        float* Wf = (float*)W4;
        #pragma unroll
        for (int k = 0; k < 2; k++) {
            int idx = t + 512*k;                   // < 1024
            int l = idx >> 1, q = idx & 1;
            float4 w = ((const float4*)W)[l*128 + (c0 >> 2) + q];
            int jrow = (l >> 2)*8;
            int e0 = l & 3;
            Wf[(jrow + q*4 + 0)*4 + e0] = w.x;
            Wf[(jrow + q*4 + 1)*4 + e0] = w.y;
            Wf[(jrow + q*4 + 2)*4 + e0] = w.z;
            Wf[(jrow + q*4 + 3)*4 + e0] = w.w;
        }
    }
    __syncthreads();

    const int b = t >> 3, c = t & 7;
    float acc = 0.f;
    #pragma unroll 8
    for (int j = 0; j < 128; j++) {
        float4 va = A4[j*65 + b];
        float4 vw = W4[j*8 + c];
        acc += va.x*vw.x + va.y*vw.y + va.z*vw.z + va.w*vw.w;
    }
    if (type) g_res[b*NDM + c0 + c] = acc + res_b[c0 + c];
    else      g_Q  [b*NDM + c0 + c] = acc;
}

// =========================================================================
// Kernel 1c: u[b,h,l] = Q[b, h*64:+64] . W_k[l, h*64:+64]  for 4 l per block.
//   g_ug = u*lnkv_g; atomicAdd partial sums into g_ugs / g_ub.
// Q row held in 64 registers; W_k tile transposed in smem (conflict-free).
// =========================================================================
__global__ void __launch_bounds__(512) k1c_u(
    const float* __restrict__ W_k,
    const float* __restrict__ lnkv_g, const float* __restrict__ lnkv_b)
{
    __shared__ float4 W_s4[64*9];     // [(lrow*16+j)]*9 + h  (pad 9 vs 8)
    __shared__ float lkg[4], lkb[4];
    const int t = threadIdx.x;
    const int l0 = blockIdx.x * 4;

    {
        int lrow = t >> 7, dm4 = t & 127;
        float4 w = ((const float4*)W_k)[(l0 + lrow)*128 + dm4];
        W_s4[(lrow*16 + (dm4 & 15))*9 + (dm4 >> 4)] = w;
    }
    if (t < 4) { lkg[t] = lnkv_g[l0 + t]; lkb[t] = lnkv_b[l0 + t]; }
    __syncthreads();

    const int b = t >> 3, h = t & 7;
    float4 Qr[16];
    const float4* Q4 = (const float4*)g_Q;
    #pragma unroll
    for (int i = 0; i < 16; i++) Qr[i] = Q4[b*128 + h*16 + i];

    float ugs_p = 0.f, ub_p = 0.f;
    #pragma unroll
    for (int l = 0; l < 4; l++) {
        float u = 0.f;
        #pragma unroll
        for (int i = 0; i < 16; i++) {
            float4 w = W_s4[(l*16 + i)*9 + h];
            u += Qr[i].x*w.x + Qr[i].y*w.y + Qr[i].z*w.z + Qr[i].w*w.w;
        }
        float ug = u * lkg[l];
        g_ug[(b*NH + h)*NL + l0 + l] = ug;
        ugs_p += ug;
        ub_p  += u * lkb[l];
    }
    atomicAdd(&g_ugs[b*NH + h], ugs_p);
    atomicAdd(&g_ub [b*NH + h], ub_p);
}

// =========================================================================
// Kernel 2: main fused pass over x_dynamic.
//  phase3: ALL 16 warps, warp subtile = 4 rows x 4 heads, raw dots + stats
//  phase4: 1 warp per head, applies LN-score formula + online softmax
//  phase5: f32x2 accumulate
// =========================================================================
__global__ void __launch_bounds__(512, 1) k2_main(const float* __restrict__ x_dyn)
{
    extern __shared__ float sm[];
    float* buf     = sm;                     // 2*32*512 = 32768
    float* ug_s    = sm + 2*TILE*NL;         // 4096
    float* sc_s    = ug_s + NH*NL;           // 8*SCP   raw dots [h][p]
    float* ea_s    = sc_s + NH*SCP;          // 8*SCP   [h][p]
    float* scale_s = ea_s + NH*SCP;          // 8
    float* mrow_s  = scale_s + NH;           // 32
    float* rrow_s  = mrow_s + TILE;          // 32
    float* mrun_s  = rrow_s + TILE;          // 8
    float* zrun_s  = mrun_s + NH;            // 8
    float* trun_s  = zrun_s + NH;            // 8
    float* ugs_s   = trun_s + NH;            // 8
    float* ub_s    = ugs_s + NH;             // 8

    const int t = threadIdx.x;
    const int split = blockIdx.x, b = blockIdx.y;
    const int lane = t & 31, wid = t >> 5;

    // load ug for this b (4096 floats)
    {
        const float4* gug4 = (const float4*)(g_ug + (size_t)b*NH*NL);
        float4* ug4 = (float4*)ug_s;
        ug4[t]       = gug4[t];
        ug4[t + 512] = gug4[t + 512];
    }
    if (t < NH) {
        ugs_s[t] = g_ugs[b*NH + t];
        ub_s [t] = g_ub [b*NH + t];
        mrun_s[t] = NEG_INF; zrun_s[t] = 0.f; trun_s[t] = 0.f;
    }

    const float* xbase = x_dyn + ((size_t)b*NP + (size_t)split*ROWS_PER_BLK)*NL;

    // prefetch tile 0 (32*512 floats = 4096 float4; 8 per thread)
    {
        uint32_t dst = s2u(buf);
        const float4* src = (const float4*)xbase;
        #pragma unroll
        for (int j = 0; j < 8; j++)
            cp_async16(dst + (uint32_t)(t + 512*j)*16u, src + t + 512*j);
        CP_COMMIT();
    }

    // phase5 thread mapping
    const int cg = t & 127;           // 16B column group
    const int hg = (t >> 7) & 1;      // head group: heads hg*4..hg*4+3
    const int pg = t >> 8;            // p half: [pg*16, pg*16+16)
    ulonglong2 A2[4];
    #pragma unroll
    for (int j = 0; j < 4; j++) { A2[j].x = 0ull; A2[j].y = 0ull; }

    // phase3 warp mapping
    const int rg  = wid >> 1;         // row group: rows rg*4..rg*4+3
    const int hgw = wid & 1;          // head group: heads hgw*4..hgw*4+3

    #pragma unroll 1
    for (int tile = 0; tile < NTILES; tile++) {
        float* xb = buf + (tile & 1)*TILE*NL;

        __syncthreads();   // prev phase5 done: safe to refill other buffer / rewrite ea_s

        if (tile + 1 < NTILES) {
            float* nb = buf + ((tile+1) & 1)*TILE*NL;
            uint32_t dst = s2u(nb);
            const float4* src = (const float4*)(xbase + (size_t)(tile+1)*TILE*NL);
            #pragma unroll
            for (int j = 0; j < 8; j++)
                cp_async16(dst + (uint32_t)(t + 512*j)*16u, src + t + 512*j);
            CP_COMMIT();
            CP_WAIT1();
        } else {
            CP_WAIT0();
        }
        __syncthreads();   // tile data visible

        // ---- phase 3: 16 warps; warp (rg,hgw): rows rg*4.., heads hgw*4.. ----
        {
            const ulonglong2* xw2 = (const ulonglong2*)xb + (rg*4)*128;
            const ulonglong2* ug2 = (const ulonglong2*)ug_s + (hgw*4)*128;
            unsigned long long d2[4][4];
            unsigned long long s2[4], q2[4];
            #pragma unroll
            for (int r = 0; r < 4; r++) {
                s2[r] = 0ull; q2[r] = 0ull;
                #pragma unroll
                for (int h = 0; h < 4; h++) d2[r][h] = 0ull;
            }
            #pragma unroll
            for (int i = 0; i < 4; i++) {
                const int idx = lane + 32*i;
                ulonglong2 u[4];
                #pragma unroll
                for (int h = 0; h < 4; h++) u[h] = ug2[h*128 + idx];
                #pragma unroll
                for (int r = 0; r < 4; r++) {
                    ulonglong2 v = xw2[r*128 + idx];
                    s2[r] = add2(s2[r], v.x);
                    s2[r] = add2(s2[r], v.y);
                    q2[r] = fma2(v.x, v.x, q2[r]);
                    q2[r] = fma2(v.y, v.y, q2[r]);
                    #pragma unroll
                    for (int h = 0; h < 4; h++) {
                        d2[r][h] = fma2(v.x, u[h].x, d2[r][h]);
                        d2[r][h] = fma2(v.y, u[h].y, d2[r][h]);
                    }
                }
            }
            float dd[16];
            #pragma unroll
            for (int r = 0; r < 4; r++)
                #pragma unroll
                for (int h = 0; h < 4; h++) dd[r*4+h] = fold2(d2[r][h]);
            // pairing butterfly: 16 values over half-warps, then merge halves
            #pragma unroll
            for (int o = 8; o >= 1; o >>= 1) {
                #pragma unroll
                for (int i = 0; i < o; i++) {
                    bool hi = (lane & o) != 0;
                    float mine   = hi ? dd[i+o] : dd[i];
                    float theirs = hi ? dd[i]   : dd[i+o];
                    dd[i] = mine + __shfl_xor_sync(0xffffffffu, theirs, o);
                }
            }
            dd[0] += __shfl_xor_sync(0xffffffffu, dd[0], 16);
            {
                const int k = lane & 15;
                const int r = k >> 2, hl = k & 3;
                if (lane < 16)
                    sc_s[(hgw*4 + hl)*SCP + rg*4 + r] = dd[0];
            }
            // stats (written by hgw==0 warps only; computed everywhere, cheap)
            float st[8];
            #pragma unroll
            for (int r = 0; r < 4; r++) { st[r] = fold2(s2[r]); st[4+r] = fold2(q2[r]); }
            #pragma unroll
            for (int o = 4; o >= 1; o >>= 1) {
                #pragma unroll
                for (int i = 0; i < o; i++) {
                    bool hi = (lane & o) != 0;
                    float mine   = hi ? st[i+o] : st[i];
                    float theirs = hi ? st[i]   : st[i+o];
                    st[i] = mine + __shfl_xor_sync(0xffffffffu, theirs, o);
                }
            }
            st[0] += __shfl_xor_sync(0xffffffffu, st[0], 8);
            st[0] += __shfl_xor_sync(0xffffffffu, st[0], 16);
            {
                float stf = st[0];
                const int r = lane & 3;
                float mean = __shfl_sync(0xffffffffu, stf, r)     * (1.f/NL);
                float sqv  = __shfl_sync(0xffffffffu, stf, 4 + r) * (1.f/NL);
                float rs   = rsqrtf(sqv - mean*mean + 1e-5f);
                if (hgw == 0 && lane < 4) {
                    mrow_s[rg*4 + lane] = mean;
                    rrow_s[rg*4 + lane] = rs;
                }
            }
        }
        __syncthreads();

        // ---- phase 4: warp w = head w; score formula + online softmax ----
        if (wid < 8) {
            const int h = wid, p = lane;
            float dot  = sc_s[h*SCP + p];
            float mean = mrow_s[p], rs = rrow_s[p];
            float s = (rs * (dot - mean * ugs_s[h]) + ub_s[h]) * 0.125f;
            float mr = mrun_s[h];
            float tmax = s;
            #pragma unroll
            for (int o = 16; o > 0; o >>= 1)
                tmax = fmaxf(tmax, __shfl_xor_sync(~0u, tmax, o));
            float mn = fmaxf(mr, tmax);
            float e  = __expf(s - mn);
            float ea = e * rs;
            float z = e, tt = ea * mean;
            #pragma unroll
            for (int o = 16; o > 0; o >>= 1) {
                z  += __shfl_xor_sync(~0u, z,  o);
                tt += __shfl_xor_sync(~0u, tt, o);
            }
            ea_s[h*SCP + p] = ea;
            g_scores[((size_t)(b*NH + h))*NP + split*ROWS_PER_BLK + tile*TILE + p] = s;
            if (lane == 0) {
                float scale = __expf(mr - mn);
                zrun_s[h] = zrun_s[h]*scale + z;
                trun_s[h] = trun_s[h]*scale + tt;
                mrun_s[h] = mn;
                scale_s[h] = scale;
            }
        }
        __syncthreads();

        // ---- phase 5: accumulate A, f32x2 ----
        {
            #pragma unroll
            for (int j = 0; j < 4; j++) {
                float sj = scale_s[hg*4 + j];
                unsigned long long sj2 = pack2(sj, sj);
                A2[j].x = mul2(A2[j].x, sj2);
                A2[j].y = mul2(A2[j].y, sj2);
            }
            const ulonglong2* xc2 = (const ulonglong2*)xb;
            #pragma unroll
            for (int pq = 0; pq < 4; pq++) {
                const int p0 = pg*16 + pq*4;
                float4 e0 = *(const float4*)&ea_s[(hg*4+0)*SCP + p0];
                float4 e1 = *(const float4*)&ea_s[(hg*4+1)*SCP + p0];
                float4 e2 = *(const float4*)&ea_s[(hg*4+2)*SCP + p0];
                float4 e3 = *(const float4*)&ea_s[(hg*4+3)*SCP + p0];
                float ev0[4] = {e0.x, e0.y, e0.z, e0.w};
                float ev1[4] = {e1.x, e1.y, e1.z, e1.w};
                float ev2[4] = {e2.x, e2.y, e2.z, e2.w};
                float ev3[4] = {e3.x, e3.y, e3.z, e3.w};
                #pragma unroll
                for (int pp = 0; pp < 4; pp++) {
                    ulonglong2 v = xc2[(p0+pp)*128 + cg];
                    unsigned long long q0 = pack2(ev0[pp], ev0[pp]);
                    unsigned long long q1 = pack2(ev1[pp], ev1[pp]);
                    unsigned long long q2_ = pack2(ev2[pp], ev2[pp]);
                    unsigned long long q3 = pack2(ev3[pp], ev3[pp]);
                    A2[0].x = fma2(q0, v.x, A2[0].x);  A2[0].y = fma2(q0, v.y, A2[0].y);
                    A2[1].x = fma2(q1, v.x, A2[1].x);  A2[1].y = fma2(q1, v.y, A2[1].y);
                    A2[2].x = fma2(q2_, v.x, A2[2].x); A2[2].y = fma2(q2_, v.y, A2[2].y);
                    A2[3].x = fma2(q3, v.x, A2[3].x);  A2[3].y = fma2(q3, v.y, A2[3].y);
                }
            }
        }
    }

    // epilogue: combine the two p-halves via smem (ug_s no longer needed)
    __syncthreads();
    if (pg == 1) {
        float4* tmp = (float4*)ug_s;
        #pragma unroll
        for (int j = 0; j < 4; j++) tmp[(hg*4+j)*128 + cg] = *(float4*)&A2[j];
    }
    __syncthreads();
    if (pg == 0) {
        const float4* tmp = (const float4*)ug_s;
        float4* pa = (float4*)(g_pa + (size_t)(b*SPLIT + split)*NH*NL);
        #pragma unroll
        for (int j = 0; j < 4; j++) {
            float4 o = tmp[(hg*4+j)*128 + cg];
            float4 a = *(float4*)&A2[j];
            o.x += a.x; o.y += a.y; o.z += a.z; o.w += a.w;
            pa[(hg*4+j)*128 + cg] = o;
        }
    }
    if (t < NH) {
        int idx = (b*SPLIT + split)*NH + t;
        g_pm[idx] = mrun_s[t];
        g_pz[idx] = zrun_s[t];
        g_pt[idx] = trun_s[t];
    }
}

// =========================================================================
// Kernel 3: combine split partials per (b,h); project through W_v;
//           write out = residual + ctx; write normalized attn row
// =========================================================================
__global__ void __launch_bounds__(256) k3_combine(
    const float* __restrict__ W_v,
    const float* __restrict__ lnkv_g, const float* __restrict__ lnkv_b,
    float* __restrict__ out)
{
    __shared__ float es[SPLIT];
    __shared__ float sT, sInvZ, sM;
    __shared__ float cvec[NL];
    __shared__ float part[4*64];

    const int t = threadIdx.x;
    const int b = blockIdx.x >> 3, h = blockIdx.x & 7;

    if (t == 0) {
        float M = NEG_INF;
        #pragma unroll
        for (int i = 0; i < SPLIT; i++)
            M = fmaxf(M, g_pm[(b*SPLIT + i)*NH + h]);
        float Z = 0.f, T = 0.f;
        #pragma unroll
        for (int i = 0; i < SPLIT; i++) {
            int idx = (b*SPLIT + i)*NH + h;
            float e = __expf(g_pm[idx] - M);
            es[i] = e;
            Z += g_pz[idx] * e;
            T += g_pt[idx] * e;
        }
        float iz = 1.f / Z;
        sT = T; sInvZ = iz; sM = M;
    }
    __syncthreads();

    for (int l = t; l < NL; l += 256) {
        float A = 0.f;
        #pragma unroll
        for (int i = 0; i < SPLIT; i++)
            A += g_pa[((size_t)(b*SPLIT + i)*NH + h)*NL + l] * es[i];
        cvec[l] = lnkv_g[l] * (A - sT) * sInvZ + lnkv_b[l];
    }
    __syncthreads();

    {
        const int d = t & 63, lg = t >> 6;
        float acc = 0.f;
        const int l0 = lg * 128;
        #pragma unroll 4
        for (int l = l0; l < l0 + 128; l++)
            acc += cvec[l] * W_v[l*NDM + h*NDK + d];
        part[lg*64 + d] = acc;
    }
    __syncthreads();
    if (t < 64) {
        float c = part[t] + part[64+t] + part[128+t] + part[192+t];
        out[b*NDM + h*NDK + t] = c + g_res[b*NDM + h*NDK + t];
    }

    // attn output row for this (b,h): exp(score - M) * invZ
    {
        const float M = sM, iz = sInvZ;
        const float4* sc4 = (const float4*)(g_scores + ((size_t)(b*NH + h))*NP);
        float4* ao = (float4*)(out + NB*NDM + ((size_t)(b*NH + h))*NP);
        #pragma unroll
        for (int j = t; j < NP/4; j += 256) {
            float4 s = sc4[j];
            float4 o;
            o.x = __expf(s.x - M) * iz;
            o.y = __expf(s.y - M) * iz;
            o.z = __expf(s.z - M) * iz;
            o.w = __expf(s.w - M) * iz;
            ao[j] = o;
        }
    }
}

// =========================================================================
extern "C" void kernel_launch(void* const* d_in, const int* in_sizes, int n_in,
                              void* d_out, int out_size)
{
    const float* x_trafic  = (const float*)d_in[0];
    const float* x_dynamic = (const float*)d_in[1];
    // d_in[2] x_known unused by the reference
    const float* W_q    = (const float*)d_in[3];
    const float* W_k    = (const float*)d_in[4];
    const float* W_v    = (const float*)d_in[5];
    const float* lnq_g  = (const float*)d_in[6];
    const float* lnq_b  = (const float*)d_in[7];
    const float* lnkv_g = (const float*)d_in[8];
    const float* lnkv_b = (const float*)d_in[9];
    const float* res_W  = (const float*)d_in[10];
    const float* res_b  = (const float*)d_in[11];
    float* out = (float*)d_out;

    const int smem1b = (128*65 + 128*8) * (int)sizeof(float4);   // ~149.5 KB
    const int smem2  = (2*TILE*NL + NH*NL + 2*NH*SCP + NH + 2*TILE + 5*NH) * (int)sizeof(float);
    cudaFuncSetAttribute(k1b_gemm, cudaFuncAttributeMaxDynamicSharedMemorySize, smem1b);
    cudaFuncSetAttribute(k2_main,  cudaFuncAttributeMaxDynamicSharedMemorySize, smem2);

    k1a_ln<<<NB, 512>>>(x_trafic, lnq_g, lnq_b);
    k1b_gemm<<<128, 512, smem1b>>>(x_trafic, W_q, res_W, res_b);
    k1c_u<<<128, 512>>>(W_k, lnkv_g, lnkv_b);
    k2_main<<<dim3(SPLIT, NB), 512, smem2>>>(x_dynamic);
    k3_combine<<<NB*NH, 256>>>(W_v, lnkv_g, lnkv_b, out);
}

// round 11
// speedup vs baseline: 1.3920x; 1.1420x over previous
#include <cuda_runtime.h>
#include <cstdint>

#define NB   64      // B
#define NP   2048    // P
#define NL   512     // L
#define NDM  512     // D_MODEL
#define NH   8       // heads
#define NDK  64
#define SPLIT 2
#define ROWS_PER_BLK (NP/SPLIT)    // 1024
#define TILE 32
#define NTILES (ROWS_PER_BLK/TILE) // 32
#define NSTG 3
#define SCSTR 33     // sc_s padded row stride

#define NEG_INF (__int_as_float(0xff800000))

// ------------------------- scratch (static device memory) -------------------------
__device__ float g_lnq[NB*NL];           // LN(x_trafic) * g + b
__device__ float g_Q[NB*NDM];            // Q = lnq @ W_q
__device__ float g_ug[NB*NH*NL];         // (u * lnkv_g) per (b,h,l)
__device__ float g_ugs[NB*NH];           // sum_l ug
__device__ float g_ub[NB*NH];            // sum_l u * lnkv_b
__device__ float g_scores[NB*NH*NP];     // raw scores
__device__ float g_pm[NB*SPLIT*NH];      // partial max
__device__ float g_pz[NB*SPLIT*NH];      // partial Z
__device__ float g_pt[NB*SPLIT*NH];      // partial T
__device__ float g_pa[NB*SPLIT*NH*NL];   // partial A (2 MB)
__device__ float g_res[NB*NDM];          // residual = x_trafic @ res_W + res_b

// ------------------------- helpers -------------------------
__device__ __forceinline__ uint32_t s2u(const void* p) {
    return (uint32_t)__cvta_generic_to_shared(p);
}
__device__ __forceinline__ void cp_async16(uint32_t s, const void* g) {
    asm volatile("cp.async.cg.shared.global [%0], [%1], 16;\n" :: "r"(s), "l"(g));
}
#define CP_COMMIT() asm volatile("cp.async.commit_group;\n")
#define CP_WAIT1()  asm volatile("cp.async.wait_group 1;\n")

// named barriers: Y (free) ids 2,3 ; X (full) ids 4,5 ; producer-internal id 6
#define BAR_SYNC512(id)   asm volatile("bar.sync %0, 512;"   :: "r"(id) : "memory")
#define BAR_ARRIVE512(id) asm volatile("bar.arrive %0, 512;" :: "r"(id) : "memory")
#define BAR_PROD()        asm volatile("bar.sync 6, 256;"    ::: "memory")

// packed fp32x2 math (Blackwell; ptxas never emits these from C++)
__device__ __forceinline__ unsigned long long fma2(unsigned long long a,
                                                   unsigned long long b,
                                                   unsigned long long c) {
    unsigned long long d;
    asm("fma.rn.f32x2 %0, %1, %2, %3;" : "=l"(d) : "l"(a), "l"(b), "l"(c));
    return d;
}
__device__ __forceinline__ unsigned long long add2(unsigned long long a,
                                                   unsigned long long b) {
    unsigned long long d;
    asm("add.rn.f32x2 %0, %1, %2;" : "=l"(d) : "l"(a), "l"(b));
    return d;
}
__device__ __forceinline__ unsigned long long mul2(unsigned long long a,
                                                   unsigned long long b) {
    unsigned long long d;
    asm("mul.rn.f32x2 %0, %1, %2;" : "=l"(d) : "l"(a), "l"(b));
    return d;
}
__device__ __forceinline__ unsigned long long pack2(float lo, float hi) {
    unsigned long long d;
    asm("mov.b64 %0, {%1, %2};" : "=l"(d) : "f"(lo), "f"(hi));
    return d;
}
__device__ __forceinline__ float fold2(unsigned long long a) {
    float lo, hi;
    asm("mov.b64 {%0, %1}, %2;" : "=f"(lo), "=f"(hi) : "l"(a));
    return lo + hi;
}

// =========================================================================
// Kernel 1a: LN of x_trafic -> g_lnq; zero ugs/ub accumulators.
// =========================================================================
__global__ void __launch_bounds__(512) k1a_ln(
    const float* __restrict__ x_trafic,
    const float* __restrict__ lnq_g, const float* __restrict__ lnq_b)
{
    __shared__ float red1[16], red2[16];
    __shared__ float sc_mean, sc_r;
    const int t = threadIdx.x, b = blockIdx.x;
    const int lane = t & 31, wid = t >> 5;

    if (b == 0) { g_ugs[t] = 0.f; g_ub[t] = 0.f; }   // NB*NH == 512

    float v = x_trafic[b*NL + t];
    float s1 = v, s2v = v*v;
    #pragma unroll
    for (int o = 16; o > 0; o >>= 1) {
        s1  += __shfl_xor_sync(~0u, s1, o);
        s2v += __shfl_xor_sync(~0u, s2v, o);
    }
    if (lane == 0) { red1[wid] = s1; red2[wid] = s2v; }
    __syncthreads();
    if (t == 0) {
        float a = 0.f, c = 0.f;
        #pragma unroll
        for (int i = 0; i < 16; i++) { a += red1[i]; c += red2[i]; }
        float mean = a * (1.f/NL);
        float var  = c * (1.f/NL) - mean*mean;
        sc_mean = mean;
        sc_r = rsqrtf(var + 1e-5f);
    }
    __syncthreads();
    g_lnq[b*NL + t] = (v - sc_mean) * sc_r * lnq_g[t] + lnq_b[t];
}

// =========================================================================
// Kernel 1b: two GEMMs C[64x512] = A @ W, W-slice shared across all b.
// =========================================================================
__global__ void __launch_bounds__(512) k1b_gemm(
    const float* __restrict__ x_trafic,
    const float* __restrict__ W_q, const float* __restrict__ res_W,
    const float* __restrict__ res_b)
{
    extern __shared__ float4 sm4[];
    float4* A4 = sm4;                 // [j=128][b=64] stride 65 (padded)
    float4* W4 = sm4 + 128*65;        // [j=128][c=8]
    const int t = threadIdx.x;
    const int type = blockIdx.x >> 6, cg = blockIdx.x & 63;
    const int c0 = cg * 8;
    const float* A = type ? x_trafic : g_lnq;
    const float* W = type ? res_W : W_q;

    {
        const float4* Asrc = (const float4*)A;
        #pragma unroll
        for (int k = 0; k < 16; k++) {
            int g = t + 512*k;
            A4[(g & 127)*65 + (g >> 7)] = Asrc[g];
        }
    }
    {
        float* Wf = (float*)W4;
        #pragma unroll
        for (int k = 0; k < 2; k++) {
            int idx = t + 512*k;
            int l = idx >> 1, q = idx & 1;
            float4 w = ((const float4*)W)[l*128 + (c0 >> 2) + q];
            int jrow = (l >> 2)*8;
            int e0 = l & 3;
            Wf[(jrow + q*4 + 0)*4 + e0] = w.x;
            Wf[(jrow + q*4 + 1)*4 + e0] = w.y;
            Wf[(jrow + q*4 + 2)*4 + e0] = w.z;
            Wf[(jrow + q*4 + 3)*4 + e0] = w.w;
        }
    }
    __syncthreads();

    const int b = t >> 3, c = t & 7;
    float acc = 0.f;
    #pragma unroll 8
    for (int j = 0; j < 128; j++) {
        float4 va = A4[j*65 + b];
        float4 vw = W4[j*8 + c];
        acc += va.x*vw.x + va.y*vw.y + va.z*vw.z + va.w*vw.w;
    }
    if (type) g_res[b*NDM + c0 + c] = acc + res_b[c0 + c];
    else      g_Q  [b*NDM + c0 + c] = acc;
}

// =========================================================================
// Kernel 1c: u[b,h,l] for 4 l per block; g_ug, partial ugs/ub via atomics.
// =========================================================================
__global__ void __launch_bounds__(512) k1c_u(
    const float* __restrict__ W_k,
    const float* __restrict__ lnkv_g, const float* __restrict__ lnkv_b)
{
    __shared__ float4 W_s4[64*9];
    __shared__ float lkg[4], lkb[4];
    const int t = threadIdx.x;
    const int l0 = blockIdx.x * 4;

    {
        int lrow = t >> 7, dm4 = t & 127;
        float4 w = ((const float4*)W_k)[(l0 + lrow)*128 + dm4];
        W_s4[(lrow*16 + (dm4 & 15))*9 + (dm4 >> 4)] = w;
    }
    if (t < 4) { lkg[t] = lnkv_g[l0 + t]; lkb[t] = lnkv_b[l0 + t]; }
    __syncthreads();

    const int b = t >> 3, h = t & 7;
    float4 Qr[16];
    const float4* Q4 = (const float4*)g_Q;
    #pragma unroll
    for (int i = 0; i < 16; i++) Qr[i] = Q4[b*128 + h*16 + i];

    float ugs_p = 0.f, ub_p = 0.f;
    #pragma unroll
    for (int l = 0; l < 4; l++) {
        float u = 0.f;
        #pragma unroll
        for (int i = 0; i < 16; i++) {
            float4 w = W_s4[(l*16 + i)*9 + h];
            u += Qr[i].x*w.x + Qr[i].y*w.y + Qr[i].z*w.z + Qr[i].w*w.w;
        }
        float ug = u * lkg[l];
        g_ug[(b*NH + h)*NL + l0 + l] = ug;
        ugs_p += ug;
        ub_p  += u * lkb[l];
    }
    atomicAdd(&g_ugs[b*NH + h], ugs_p);
    atomicAdd(&g_ub [b*NH + h], ub_p);
}

// =========================================================================
// Kernel 2: warp-specialized producer/consumer pipeline over x_dynamic.
//  producers (warps 0-7):  cp.async loads, phase3 dots+stats, phase4 softmax
//  consumers (warps 8-15): phase5 context accumulation on previous tile
//  3-stage x buffer; double-buffered ea/scale; named-barrier handshake.
// =========================================================================
__global__ void __launch_bounds__(512, 1) k2_main(const float* __restrict__ x_dyn)
{
    extern __shared__ float sm[];
    float* buf     = sm;                       // NSTG*32*512 = 49152
    float* ug_s    = sm + NSTG*TILE*NL;        // 4096
    float* sc_s    = ug_s + NH*NL;             // 8*33 = 264
    float* ea_s    = sc_s + NH*SCSTR;          // 2*256 = 512
    float* scale_s = ea_s + 2*NH*TILE;         // 16
    float* mrow_s  = scale_s + 16;             // 32
    float* rrow_s  = mrow_s + TILE;            // 32

    const int t = threadIdx.x;
    const int split = blockIdx.x, b = blockIdx.y;
    const int lane = t & 31, wid = t >> 5;

    // all 512 threads load ug (4096 floats)
    {
        const float4* gug4 = (const float4*)(g_ug + (size_t)b*NH*NL);
        float4* ug4 = (float4*)ug_s;
        ug4[t]       = gug4[t];
        ug4[t + 512] = gug4[t + 512];
    }
    __syncthreads();

    const float* xbase = x_dyn + ((size_t)b*NP + (size_t)split*ROWS_PER_BLK)*NL;

    if (wid < 8) {
        // =================== PRODUCER (warps 0-7) ===================
        const int tp = t;                          // 0..255
        const float ugs_r = g_ugs[b*NH + (lane & 7)];
        const float ub_r  = g_ub [b*NH + (lane & 7)];
        float mr = NEG_INF, zr = 0.f, tr = 0.f;    // online softmax state (warp=head)

        // prefetch tile 0 into stage 0
        {
            uint32_t dst = s2u(buf);
            const float4* src = (const float4*)xbase;
            #pragma unroll
            for (int j = 0; j < 16; j++)
                cp_async16(dst + (uint32_t)(tp + 256*j)*16u, src + tp + 256*j);
            CP_COMMIT();
        }

        int st_cur = 0, st_nxt = 1;
        #pragma unroll 1
        for (int tile = 0; tile < NTILES; tile++) {
            if (tile >= 2) BAR_SYNC512(2 + (tile & 1));   // consumer done tile-2

            if (tile + 1 < NTILES) {
                uint32_t dst = s2u(buf + st_nxt*TILE*NL);
                const float4* src = (const float4*)(xbase + (size_t)(tile+1)*TILE*NL);
                #pragma unroll
                for (int j = 0; j < 16; j++)
                    cp_async16(dst + (uint32_t)(tp + 256*j)*16u, src + tp + 256*j);
            }
            CP_COMMIT();
            CP_WAIT1();          // tile's data arrived (this thread)
            BAR_PROD();          // visible to all producers; sc_s free

            // ---- phase 3: warp wid -> rows wid*4..+3, all 8 heads ----
            {
                const ulonglong2* xw2 = (const ulonglong2*)(buf + st_cur*TILE*NL) + (wid*4)*128;
                const ulonglong2* ug2 = (const ulonglong2*)ug_s;
                unsigned long long d2[4][8];
                unsigned long long s2[4], q2[4];
                #pragma unroll
                for (int r = 0; r < 4; r++) {
                    s2[r] = 0ull; q2[r] = 0ull;
                    #pragma unroll
                    for (int h = 0; h < 8; h++) d2[r][h] = 0ull;
                }
                #pragma unroll
                for (int i = 0; i < 4; i++) {
                    const int idx = lane + 32*i;
                    ulonglong2 u[8];
                    #pragma unroll
                    for (int h = 0; h < 8; h++) u[h] = ug2[h*128 + idx];
                    #pragma unroll
                    for (int r = 0; r < 4; r++) {
                        ulonglong2 v = xw2[r*128 + idx];
                        s2[r] = add2(s2[r], v.x);
                        s2[r] = add2(s2[r], v.y);
                        q2[r] = fma2(v.x, v.x, q2[r]);
                        q2[r] = fma2(v.y, v.y, q2[r]);
                        #pragma unroll
                        for (int h = 0; h < 8; h++) {
                            d2[r][h] = fma2(v.x, u[h].x, d2[r][h]);
                            d2[r][h] = fma2(v.y, u[h].y, d2[r][h]);
                        }
                    }
                }
                float dd[32], st[8];
                #pragma unroll
                for (int r = 0; r < 4; r++) {
                    st[r]   = fold2(s2[r]);
                    st[4+r] = fold2(q2[r]);
                    #pragma unroll
                    for (int h = 0; h < 8; h++) dd[r*8+h] = fold2(d2[r][h]);
                }
                // butterfly multi-value reduce: lane k ends with sum of dd[k]
                #pragma unroll
                for (int o = 16; o >= 1; o >>= 1) {
                    #pragma unroll
                    for (int i = 0; i < o; i++) {
                        bool hi = (lane & o) != 0;
                        float mine   = hi ? dd[i+o] : dd[i];
                        float theirs = hi ? dd[i]   : dd[i+o];
                        dd[i] = mine + __shfl_xor_sync(0xffffffffu, theirs, o);
                    }
                }
                // stats: lane k ends with st[k&7]
                #pragma unroll
                for (int o = 16; o >= 8; o >>= 1) {
                    #pragma unroll
                    for (int i = 0; i < 8; i++)
                        st[i] += __shfl_xor_sync(0xffffffffu, st[i], o);
                }
                #pragma unroll
                for (int o = 4; o >= 1; o >>= 1) {
                    #pragma unroll
                    for (int i = 0; i < o; i++) {
                        bool hi = (lane & o) != 0;
                        float mine   = hi ? st[i+o] : st[i];
                        float theirs = hi ? st[i]   : st[i+o];
                        st[i] = mine + __shfl_xor_sync(0xffffffffu, theirs, o);
                    }
                }

                const int r = lane >> 3, h = lane & 7;
                float sfin = st[0];
                float mean = __shfl_sync(0xffffffffu, sfin, r) * (1.f/NL);
                float sqv  = __shfl_sync(0xffffffffu, sfin, r + 4) * (1.f/NL);
                float rs   = rsqrtf(sqv - mean*mean + 1e-5f);
                float s = (rs * (dd[0] - mean * ugs_r) + ub_r) * 0.125f;
                sc_s[h*SCSTR + wid*4 + r] = s;
                if (h == 0) { mrow_s[wid*4 + r] = mean; rrow_s[wid*4 + r] = rs; }
            }
            BAR_PROD();          // sc/mrow/rrow ready

            // ---- phase 4: warp wid = head wid; softmax over 32 p ----
            {
                const int p = lane;
                float s = sc_s[wid*SCSTR + p];
                float tmax = s;
                #pragma unroll
                for (int o = 16; o > 0; o >>= 1)
                    tmax = fmaxf(tmax, __shfl_xor_sync(~0u, tmax, o));
                float mn = fmaxf(mr, tmax);
                float e  = __expf(s - mn);
                float ea = e * rrow_s[p];
                float z = e, tt = ea * mrow_s[p];
                #pragma unroll
                for (int o = 16; o > 0; o >>= 1) {
                    z  += __shfl_xor_sync(~0u, z,  o);
                    tt += __shfl_xor_sync(~0u, tt, o);
                }
                float scale = __expf(mr - mn);
                zr = zr*scale + z;
                tr = tr*scale + tt;
                mr = mn;
                ea_s[(tile & 1)*NH*TILE + wid*TILE + p] = ea;
                if (lane == 0) scale_s[(tile & 1)*NH + wid] = scale;
                g_scores[((size_t)(b*NH + wid))*NP + split*ROWS_PER_BLK + tile*TILE + p] = s;
            }
            BAR_ARRIVE512(4 + (tile & 1));   // signal full

            st_cur = st_nxt;
            st_nxt = (st_nxt + 1 == NSTG) ? 0 : st_nxt + 1;
        }

        if (lane == 0) {
            int idx = (b*SPLIT + split)*NH + wid;
            g_pm[idx] = mr;
            g_pz[idx] = zr;
            g_pt[idx] = tr;
        }
    } else {
        // =================== CONSUMER (warps 8-15) ===================
        const int tc = t - 256;            // 0..255
        const int cg = tc & 127;           // 16B column group
        const int hgc = tc >> 7;           // heads hgc*4..hgc*4+3
        ulonglong2 A2[4];
        #pragma unroll
        for (int j = 0; j < 4; j++) { A2[j].x = 0ull; A2[j].y = 0ull; }

        int st_cur = 0;
        #pragma unroll 1
        for (int tile = 0; tile < NTILES; tile++) {
            BAR_SYNC512(4 + (tile & 1));   // wait full

            const float* eab = ea_s + (tile & 1)*NH*TILE;
            #pragma unroll
            for (int j = 0; j < 4; j++) {
                float sj = scale_s[(tile & 1)*NH + hgc*4 + j];
                unsigned long long sj2 = pack2(sj, sj);
                A2[j].x = mul2(A2[j].x, sj2);
                A2[j].y = mul2(A2[j].y, sj2);
            }
            const ulonglong2* xc2 = (const ulonglong2*)(buf + st_cur*TILE*NL);
            #pragma unroll
            for (int pq = 0; pq < 8; pq++) {
                const int p0 = pq*4;
                float4 e0 = *(const float4*)&eab[(hgc*4+0)*TILE + p0];
                float4 e1 = *(const float4*)&eab[(hgc*4+1)*TILE + p0];
                float4 e2 = *(const float4*)&eab[(hgc*4+2)*TILE + p0];
                float4 e3 = *(const float4*)&eab[(hgc*4+3)*TILE + p0];
                float ev0[4] = {e0.x, e0.y, e0.z, e0.w};
                float ev1[4] = {e1.x, e1.y, e1.z, e1.w};
                float ev2[4] = {e2.x, e2.y, e2.z, e2.w};
                float ev3[4] = {e3.x, e3.y, e3.z, e3.w};
                #pragma unroll
                for (int pp = 0; pp < 4; pp++) {
                    ulonglong2 v = xc2[(p0+pp)*128 + cg];
                    unsigned long long q0 = pack2(ev0[pp], ev0[pp]);
                    unsigned long long q1 = pack2(ev1[pp], ev1[pp]);
                    unsigned long long q2_ = pack2(ev2[pp], ev2[pp]);
                    unsigned long long q3 = pack2(ev3[pp], ev3[pp]);
                    A2[0].x = fma2(q0, v.x, A2[0].x);  A2[0].y = fma2(q0, v.y, A2[0].y);
                    A2[1].x = fma2(q1, v.x, A2[1].x);  A2[1].y = fma2(q1, v.y, A2[1].y);
                    A2[2].x = fma2(q2_, v.x, A2[2].x); A2[2].y = fma2(q2_, v.y, A2[2].y);
                    A2[3].x = fma2(q3, v.x, A2[3].x);  A2[3].y = fma2(q3, v.y, A2[3].y);
                }
            }
            BAR_ARRIVE512(2 + (tile & 1));   // signal free

            st_cur = (st_cur + 1 == NSTG) ? 0 : st_cur + 1;
        }

        // write partial A
        float4* pa = (float4*)(g_pa + (size_t)(b*SPLIT + split)*NH*NL);
        #pragma unroll
        for (int j = 0; j < 4; j++)
            pa[(hgc*4+j)*128 + cg] = *(float4*)&A2[j];
    }
}

// =========================================================================
// Kernel 3: combine split partials per (b,h); project through W_v;
//           write out = residual + ctx; write normalized attn row
// =========================================================================
__global__ void __launch_bounds__(256) k3_combine(
    const float* __restrict__ W_v,
    const float* __restrict__ lnkv_g, const float* __restrict__ lnkv_b,
    float* __restrict__ out)
{
    __shared__ float es[SPLIT];
    __shared__ float sT, sInvZ, sM;
    __shared__ float cvec[NL];
    __shared__ float part[4*64];

    const int t = threadIdx.x;
    const int b = blockIdx.x >> 3, h = blockIdx.x & 7;

    if (t == 0) {
        float M = NEG_INF;
        #pragma unroll
        for (int i = 0; i < SPLIT; i++)
            M = fmaxf(M, g_pm[(b*SPLIT + i)*NH + h]);
        float Z = 0.f, T = 0.f;
        #pragma unroll
        for (int i = 0; i < SPLIT; i++) {
            int idx = (b*SPLIT + i)*NH + h;
            float e = __expf(g_pm[idx] - M);
            es[i] = e;
            Z += g_pz[idx] * e;
            T += g_pt[idx] * e;
        }
        float iz = 1.f / Z;
        sT = T; sInvZ = iz; sM = M;
    }
    __syncthreads();

    for (int l = t; l < NL; l += 256) {
        float A = 0.f;
        #pragma unroll
        for (int i = 0; i < SPLIT; i++)
            A += g_pa[((size_t)(b*SPLIT + i)*NH + h)*NL + l] * es[i];
        cvec[l] = lnkv_g[l] * (A - sT) * sInvZ + lnkv_b[l];
    }
    __syncthreads();

    {
        const int d = t & 63, lg = t >> 6;
        float acc = 0.f;
        const int l0 = lg * 128;
        #pragma unroll 4
        for (int l = l0; l < l0 + 128; l++)
            acc += cvec[l] * W_v[l*NDM + h*NDK + d];
        part[lg*64 + d] = acc;
    }
    __syncthreads();
    if (t < 64) {
        float c = part[t] + part[64+t] + part[128+t] + part[192+t];
        out[b*NDM + h*NDK + t] = c + g_res[b*NDM + h*NDK + t];
    }

    // attn output row for this (b,h): exp(score - M) * invZ
    {
        const float M = sM, iz = sInvZ;
        const float4* sc4 = (const float4*)(g_scores + ((size_t)(b*NH + h))*NP);
        float4* ao = (float4*)(out + NB*NDM + ((size_t)(b*NH + h))*NP);
        #pragma unroll
        for (int j = t; j < NP/4; j += 256) {
            float4 s = sc4[j];
            float4 o;
            o.x = __expf(s.x - M) * iz;
            o.y = __expf(s.y - M) * iz;
            o.z = __expf(s.z - M) * iz;
            o.w = __expf(s.w - M) * iz;
            ao[j] = o;
        }
    }
}

// =========================================================================
extern "C" void kernel_launch(void* const* d_in, const int* in_sizes, int n_in,
                              void* d_out, int out_size)
{
    const float* x_trafic  = (const float*)d_in[0];
    const float* x_dynamic = (const float*)d_in[1];
    // d_in[2] x_known unused by the reference
    const float* W_q    = (const float*)d_in[3];
    const float* W_k    = (const float*)d_in[4];
    const float* W_v    = (const float*)d_in[5];
    const float* lnq_g  = (const float*)d_in[6];
    const float* lnq_b  = (const float*)d_in[7];
    const float* lnkv_g = (const float*)d_in[8];
    const float* lnkv_b = (const float*)d_in[9];
    const float* res_W  = (const float*)d_in[10];
    const float* res_b  = (const float*)d_in[11];
    float* out = (float*)d_out;

    const int smem1b = (128*65 + 128*8) * (int)sizeof(float4);   // ~149.5 KB
    const int smem2  = (NSTG*TILE*NL + NH*NL + NH*SCSTR + 2*NH*TILE + 16 + 2*TILE)
                       * (int)sizeof(float);                     // ~211.4 KB
    cudaFuncSetAttribute(k1b_gemm, cudaFuncAttributeMaxDynamicSharedMemorySize, smem1b);
    cudaFuncSetAttribute(k2_main,  cudaFuncAttributeMaxDynamicSharedMemorySize, smem2);

    k1a_ln<<<NB, 512>>>(x_trafic, lnq_g, lnq_b);
    k1b_gemm<<<128, 512, smem1b>>>(x_trafic, W_q, res_W, res_b);
    k1c_u<<<128, 512>>>(W_k, lnkv_g, lnkv_b);
    k2_main<<<dim3(SPLIT, NB), 512, smem2>>>(x_dynamic);
    k3_combine<<<NB*NH, 256>>>(W_v, lnkv_g, lnkv_b, out);
}